// round 2
// baseline (speedup 1.0000x reference)
#include <cuda_runtime.h>
#include <math.h>

// ---------------------------------------------------------------------------
// Scratch (allocation-free rule: __device__ globals)
// ---------------------------------------------------------------------------
#define MAXN 131072
__device__ float  g_in_sums[MAXN];
__device__ float  g_out_sums[MAXN];
// g_acc: [0]=focal_sum [1]=coverage_sum [2]=tour_sum [3]=demand_sum
//        [4]=masked_sq_sum [5]=mask_count
__device__ double g_acc[8];
__device__ int    g_idx64;   // 1 if edge_index is int64, 0 if int32

// ---------------------------------------------------------------------------
// Kernel 0: detect edge_index dtype.
// If int64 (values < 2^31), the high 32-bit word of each index is 0.
// If int32, those words hold other random indices in [0, 100000) —
// probability all 32 are zero is ~1e-160.
// ---------------------------------------------------------------------------
__global__ void detect_kernel(const int* __restrict__ ei) {
    if (threadIdx.x == 0 && blockIdx.x == 0) {
        int all_hi_zero = 1;
        #pragma unroll
        for (int k = 0; k < 32; k++) {
            if (ei[2 * k + 1] != 0) { all_hi_zero = 0; break; }
        }
        g_idx64 = all_hi_zero;
    }
}

// ---------------------------------------------------------------------------
// Kernel 1: zero scratch (must run every replay — graph replays N times)
// ---------------------------------------------------------------------------
__global__ void zero_kernel(int n) {
    int i = blockIdx.x * blockDim.x + threadIdx.x;
    if (i < n) {
        g_in_sums[i]  = 0.0f;
        g_out_sums[i] = 0.0f;
    }
    if (blockIdx.x == 0 && threadIdx.x < 8) g_acc[threadIdx.x] = 0.0;
}

// ---------------------------------------------------------------------------
// Block reduction helper: warp shuffle + shared
// ---------------------------------------------------------------------------
__device__ __forceinline__ float block_reduce_sum(float v, float* sh) {
    const int lane = threadIdx.x & 31;
    const int wid  = threadIdx.x >> 5;
    #pragma unroll
    for (int o = 16; o > 0; o >>= 1) v += __shfl_down_sync(0xffffffffu, v, o);
    if (lane == 0) sh[wid] = v;
    __syncthreads();
    const int nwarps = blockDim.x >> 5;
    v = (threadIdx.x < nwarps) ? sh[threadIdx.x] : 0.0f;
    if (wid == 0) {
        #pragma unroll
        for (int o = 16; o > 0; o >>= 1) v += __shfl_down_sync(0xffffffffu, v, o);
    }
    __syncthreads();   // sh reused by caller for next quantity
    return v;          // valid in thread 0
}

// ---------------------------------------------------------------------------
// Kernel 2: edge pass
//   - sigmoid(edge_predictions) scattered into in/out segment sums (float RED)
//   - focal loss partial sum -> double accumulator
// Per edge: z = exp(-|l|); r = 1/(1+z); p = (l>=0) ? r : 1-r
//           bce = max(l,0) - l*t - ln(r)      (since log1p(z) = -ln(r))
//           (1-p_t) = p + t - 2pt ; alpha_t = 0.75 - 0.5t
// ---------------------------------------------------------------------------
__device__ __forceinline__ void edge_body(float l, float t, int s, int d,
                                          float& fsum) {
    float z = __expf(-fabsf(l));
    float r = __frcp_rn(1.0f + z);
    float p = (l >= 0.0f) ? r : (1.0f - r);
    float bce = fmaxf(l, 0.0f) - l * t - __logf(r);
    float ompt = p + t - 2.0f * p * t;        // 1 - p_t
    float at   = 0.75f - 0.5f * t;            // alpha_t
    fsum += at * ompt * ompt * bce;
    atomicAdd(&g_out_sums[s], p);
    atomicAdd(&g_in_sums[d], p);
}

__global__ void __launch_bounds__(256)
edge_kernel(const float* __restrict__ ep, const float* __restrict__ ye,
            const void* __restrict__ ei, int E) {
    __shared__ float sh[32];
    float fsum = 0.0f;
    const int tid    = blockIdx.x * blockDim.x + threadIdx.x;
    const int stride = gridDim.x * blockDim.x;
    const bool is64  = (g_idx64 != 0);

    int base = tid * 4;

    if (!is64) {
        const int* __restrict__ src = (const int*)ei;
        const int* __restrict__ dst = src + E;
        for (; base + 3 < E; base += stride * 4) {
            float4 l4 = *reinterpret_cast<const float4*>(ep + base);
            float4 t4 = *reinterpret_cast<const float4*>(ye + base);
            int4   s4 = *reinterpret_cast<const int4*>(src + base);
            int4   d4 = *reinterpret_cast<const int4*>(dst + base);
            edge_body(l4.x, t4.x, s4.x, d4.x, fsum);
            edge_body(l4.y, t4.y, s4.y, d4.y, fsum);
            edge_body(l4.z, t4.z, s4.z, d4.z, fsum);
            edge_body(l4.w, t4.w, s4.w, d4.w, fsum);
        }
        for (int i = base; i < E && i < base + 4; i++)
            edge_body(ep[i], ye[i], src[i], dst[i], fsum);
    } else {
        const long long* __restrict__ src = (const long long*)ei;
        const long long* __restrict__ dst = src + E;
        for (; base + 3 < E; base += stride * 4) {
            float4    l4  = *reinterpret_cast<const float4*>(ep + base);
            float4    t4  = *reinterpret_cast<const float4*>(ye + base);
            longlong2 s01 = *reinterpret_cast<const longlong2*>(src + base);
            longlong2 s23 = *reinterpret_cast<const longlong2*>(src + base + 2);
            longlong2 d01 = *reinterpret_cast<const longlong2*>(dst + base);
            longlong2 d23 = *reinterpret_cast<const longlong2*>(dst + base + 2);
            edge_body(l4.x, t4.x, (int)s01.x, (int)d01.x, fsum);
            edge_body(l4.y, t4.y, (int)s01.y, (int)d01.y, fsum);
            edge_body(l4.z, t4.z, (int)s23.x, (int)d23.x, fsum);
            edge_body(l4.w, t4.w, (int)s23.y, (int)d23.y, fsum);
        }
        for (int i = base; i < E && i < base + 4; i++)
            edge_body(ep[i], ye[i], (int)src[i], (int)dst[i], fsum);
    }

    float bsum = block_reduce_sum(fsum, sh);
    if (threadIdx.x == 0) atomicAdd(&g_acc[0], (double)bsum);
}

// ---------------------------------------------------------------------------
// Kernel 3: node pass — 5 fused reductions
// ---------------------------------------------------------------------------
__global__ void __launch_bounds__(256)
node_kernel(const float* __restrict__ node_pred,
            const float* __restrict__ x,
            const float* __restrict__ y_nodes,
            int N) {
    __shared__ float sh[32];
    float cov = 0.0f, tour = 0.0f, dem = 0.0f, sq = 0.0f, cnt = 0.0f;

    for (int i = blockIdx.x * blockDim.x + threadIdx.x; i < N;
         i += gridDim.x * blockDim.x) {
        float ins  = g_in_sums[i];
        float outs = g_out_sums[i];
        float diff = ins - outs;
        tour += diff * diff;
        if (i > 0) {
            float a = ins - 1.0f, b = outs - 1.0f;
            cov += a * a + b * b;
            dem += x[i * 4 + 2];
        }
        float y = y_nodes[i];
        float m = (y >= 0.0f) ? 1.0f : 0.0f;
        float e = node_pred[i] - y;
        sq  += m * e * e;
        cnt += m;
    }

    float v;
    v = block_reduce_sum(cov,  sh); if (threadIdx.x == 0) atomicAdd(&g_acc[1], (double)v);
    v = block_reduce_sum(tour, sh); if (threadIdx.x == 0) atomicAdd(&g_acc[2], (double)v);
    v = block_reduce_sum(dem,  sh); if (threadIdx.x == 0) atomicAdd(&g_acc[3], (double)v);
    v = block_reduce_sum(sq,   sh); if (threadIdx.x == 0) atomicAdd(&g_acc[4], (double)v);
    v = block_reduce_sum(cnt,  sh); if (threadIdx.x == 0) atomicAdd(&g_acc[5], (double)v);
}

// ---------------------------------------------------------------------------
// Kernel 4: finalize (single thread)
// ---------------------------------------------------------------------------
__global__ void finalize_kernel(const float* __restrict__ capacity,
                                float* __restrict__ out, int N, int E) {
    double denom_cov = 2.0 * (double)((N - 1) > 1 ? (N - 1) : 1);
    double coverage  = g_acc[1] / denom_cov;
    double tour      = g_acc[2] / (double)N;
    double in0  = (double)g_in_sums[0];
    double out0 = (double)g_out_sums[0];
    double depot = (in0 - out0) * (in0 - out0);
    double cap_value = (double)capacity[0];        // mean of 1 element
    double expected_tours = ceil(g_acc[3] / cap_value);
    double capacity_tours = (out0 - expected_tours) * (out0 - expected_tours);
    double similarity = g_acc[0] / (double)E;
    double node_loss  = g_acc[4] / fmax(g_acc[5], 1.0);
    double total = coverage * 5.0 + tour * 3.0 + depot * 2.0 +
                   capacity_tours * 1.5 + similarity * 0.3 + node_loss * 0.1;
    out[0] = (float)total;
}

// ---------------------------------------------------------------------------
// kernel_launch
// Inputs (metadata order):
//   0: edge_predictions f32 [E]
//   1: node_predictions f32 [N]
//   2: x                f32 [N,4]
//   3: capacity         f32 [1]
//   4: y_edges          f32 [E]
//   5: y_nodes          f32 [N]
//   6: edge_index       int (32 or 64, detected on device) [2,E]
//   7: num_nodes        (scalar; ignored — N taken from in_sizes[1])
// ---------------------------------------------------------------------------
extern "C" void kernel_launch(void* const* d_in, const int* in_sizes, int n_in,
                              void* d_out, int out_size) {
    const float* ep  = (const float*)d_in[0];
    const float* npr = (const float*)d_in[1];
    const float* x   = (const float*)d_in[2];
    const float* cap = (const float*)d_in[3];
    const float* ye  = (const float*)d_in[4];
    const float* yn  = (const float*)d_in[5];
    const void*  ei  = d_in[6];

    const int E = in_sizes[0];
    const int N = in_sizes[1];

    float* out = (float*)d_out;

    // 0. detect index dtype (device-side, deterministic)
    detect_kernel<<<1, 32>>>((const int*)ei);
    // 1. zero scratch
    {
        int blocks = (N + 255) / 256;
        zero_kernel<<<blocks, 256>>>(N);
    }
    // 2. edge pass (grid-stride, 4 edges/thread/iter)
    edge_kernel<<<2368, 256>>>(ep, ye, ei, E);
    // 3. node pass
    {
        int blocks = (N + 255) / 256;
        node_kernel<<<blocks, 256>>>(npr, x, yn, N);
    }
    // 4. finalize
    finalize_kernel<<<1, 1>>>(cap, out, N, E);
}